// round 8
// baseline (speedup 1.0000x reference)
#include <cuda_runtime.h>

// Problem constants (fixed shapes for this problem)
#define NB 4       // batch
#define CC 32      // channels (C_in == C_out)
#define NN 10000   // nodes
#define TT 12      // time steps
#define EMAX 160000
#define FF (CC*TT)         // 384 features per (b,n)
#define BNT (NB*NN*TT)     // 480000
#define TOT (NB*NN*FF)     // 15,360,000

// Scratch (device globals; no allocation allowed)
__device__ __align__(16) float  g_h  [TOT];   // [B][N][T][C]
__device__ __align__(16) float  g_agg[TOT];   // [B][N][T][C]
__device__ int    g_deg[NN+1];
__device__ int    g_row[NN+1];
__device__ int    g_cur[NN];
__device__ int    g_srcs[EMAX];
__device__ float  g_ws  [EMAX];
__device__ double g_sum [CC];
__device__ double g_sumsq[CC];
__device__ float  g_scale[CC];
__device__ float  g_shift[CC];
__device__ int    g_is64;

// ---------------- detect edge_index dtype (int32 vs int64) ----------------
// Under int64 layout: high word of every 64-bit slot is 0 (indices in [0,1e4)).
// Under int32 layout: those words are arbitrary node indices, virtually never
// ALL zero across E=160000 samples. Reads only the first 2E int32 words,
// which is in-bounds under both interpretations.
__global__ void k_detect(const int* __restrict__ ei, int E) {
    __shared__ int cnt;
    if (threadIdx.x == 0) cnt = 0;
    __syncthreads();
    int local = 0;
    for (int i = threadIdx.x; i < E; i += blockDim.x)
        if (ei[2 * i + 1] != 0) local++;
    for (int off = 16; off; off >>= 1)
        local += __shfl_down_sync(0xffffffffu, local, off);
    if ((threadIdx.x & 31) == 0 && local) atomicAdd(&cnt, local);
    __syncthreads();
    if (threadIdx.x == 0) g_is64 = (cnt == 0) ? 1 : 0;
}

__device__ __forceinline__ int load_idx(const void* eiv, long long pos) {
    if (g_is64) return (int)((const long long*)eiv)[pos];
    return ((const int*)eiv)[pos];
}

// ---------------- zero counters ----------------
__global__ void k_zero() {
    int i = blockIdx.x * blockDim.x + threadIdx.x;
    if (i < NN + 1) g_deg[i] = 0;
    if (i < CC) { g_sum[i] = 0.0; g_sumsq[i] = 0.0; }
}

// ---------------- linear: h[b][n][t][c] = sum_ci x[b][ci][n][t] * W[ci][c] ----------------
__global__ void k_linear(const float* __restrict__ x, const float* __restrict__ W) {
    __shared__ __align__(16) float ws[CC * CC];
    int tid = threadIdx.x;
    for (int i = tid; i < CC * CC; i += blockDim.x) ws[i] = W[i];
    __syncthreads();

    int gid = blockIdx.x * blockDim.x + tid;   // enumerates (b, n, t)
    if (gid >= BNT) return;
    int b = gid / (NN * TT);
    int r = gid % (NN * TT);                   // n*TT + t

    const float* xp = x + (size_t)b * CC * NN * TT + r;
    float xv[CC];
#pragma unroll
    for (int c = 0; c < CC; c++) xv[c] = xp[c * (NN * TT)];

    float4 acc[8];
#pragma unroll
    for (int d = 0; d < 8; d++) acc[d] = make_float4(0.f, 0.f, 0.f, 0.f);

    const float4* w4 = (const float4*)ws;      // [c][8] float4 rows of W
#pragma unroll
    for (int c = 0; c < CC; c++) {
        float xc = xv[c];
#pragma unroll
        for (int d = 0; d < 8; d++) {
            float4 w = w4[c * 8 + d];
            acc[d].x = fmaf(xc, w.x, acc[d].x);
            acc[d].y = fmaf(xc, w.y, acc[d].y);
            acc[d].z = fmaf(xc, w.z, acc[d].z);
            acc[d].w = fmaf(xc, w.w, acc[d].w);
        }
    }
    float4* hp = (float4*)&g_h[(size_t)gid * CC];
#pragma unroll
    for (int d = 0; d < 8; d++) hp[d] = acc[d];
}

// ---------------- degree histogram ----------------
__global__ void k_hist(const void* __restrict__ eiv, int E) {
    int e = blockIdx.x * blockDim.x + threadIdx.x;
    if (e >= E) return;
    int dst = load_idx(eiv, (long long)E + e);
    if ((unsigned)dst < NN) atomicAdd(&g_deg[dst], 1);
}

// ---------------- exclusive scan over degrees (single block) ----------------
__global__ void k_scan() {
    __shared__ int sp[1024];
    int tid = threadIdx.x;
    const int CH = (NN + 1023) / 1024;  // 10
    int base = tid * CH;
    int s = 0;
    for (int k = 0; k < CH; k++) { int i = base + k; if (i < NN) s += g_deg[i]; }
    sp[tid] = s;
    __syncthreads();
    for (int off = 1; off < 1024; off <<= 1) {
        int v = (tid >= off) ? sp[tid - off] : 0;
        __syncthreads();
        sp[tid] += v;
        __syncthreads();
    }
    int run = sp[tid] - s;  // exclusive prefix of this chunk
    for (int k = 0; k < CH; k++) {
        int i = base + k;
        if (i < NN) { g_row[i] = run; g_cur[i] = run; run += g_deg[i]; }
    }
    if (tid == 1023) g_row[NN] = sp[1023];
}

// ---------------- fill CSR ----------------
__global__ void k_fill(const void* __restrict__ eiv, const float* __restrict__ ew, int E) {
    int e = blockIdx.x * blockDim.x + threadIdx.x;
    if (e >= E) return;
    int dst = load_idx(eiv, (long long)E + e);
    if ((unsigned)dst >= NN) return;          // matches k_hist skip
    int src = load_idx(eiv, e);
    int p = atomicAdd(&g_cur[dst], 1);
    if ((unsigned)src < NN) {
        g_srcs[p] = src;
        g_ws[p]   = ew[e];
    } else {                                  // keep CSR slot consistent, zero-weight
        g_srcs[p] = 0;
        g_ws[p]   = 0.f;
    }
}

// ---------------- gather: agg[b][dst][:] = bias + sum_e w_e * h[b][src_e][:] ----------------
__global__ void k_gather(const float* __restrict__ bias) {
    int wid  = (blockIdx.x * blockDim.x + threadIdx.x) >> 5;
    int lane = threadIdx.x & 31;
    if (wid >= NB * NN) return;
    int b = wid / NN;
    int n = wid % NN;

    float4 a0 = make_float4(0.f, 0.f, 0.f, 0.f), a1 = a0, a2 = a0;
    int e0 = g_row[n], e1 = g_row[n + 1];
    const float4* hb = (const float4*)g_h;
    int browbase = b * NN;

    for (int e = e0; e < e1; e++) {
        float w = g_ws[e];
        const float4* hr = hb + (size_t)(browbase + g_srcs[e]) * (FF / 4) + lane;
        float4 v0 = hr[0], v1 = hr[32], v2 = hr[64];
        a0.x = fmaf(w, v0.x, a0.x); a0.y = fmaf(w, v0.y, a0.y);
        a0.z = fmaf(w, v0.z, a0.z); a0.w = fmaf(w, v0.w, a0.w);
        a1.x = fmaf(w, v1.x, a1.x); a1.y = fmaf(w, v1.y, a1.y);
        a1.z = fmaf(w, v1.z, a1.z); a1.w = fmaf(w, v1.w, a1.w);
        a2.x = fmaf(w, v2.x, a2.x); a2.y = fmaf(w, v2.y, a2.y);
        a2.z = fmaf(w, v2.z, a2.z); a2.w = fmaf(w, v2.w, a2.w);
    }

    int cb = (lane * 4) & 31;   // channel of .x component (same for all 3 float4 chunks)
    float4 bb = make_float4(bias[cb], bias[cb + 1], bias[cb + 2], bias[cb + 3]);
    a0.x += bb.x; a0.y += bb.y; a0.z += bb.z; a0.w += bb.w;
    a1.x += bb.x; a1.y += bb.y; a1.z += bb.z; a1.w += bb.w;
    a2.x += bb.x; a2.y += bb.y; a2.z += bb.z; a2.w += bb.w;

    float4* ap = (float4*)&g_agg[(size_t)(browbase + n) * FF] + lane;
    ap[0] = a0; ap[32] = a1; ap[64] = a2;
}

// ---------------- per-channel sum / sumsq ----------------
__global__ void k_stats() {
    int tid = blockIdx.x * blockDim.x + threadIdx.x;
    int stride = gridDim.x * blockDim.x;   // multiple of 32
    int lane = threadIdx.x & 31;
    float s = 0.f, ss = 0.f;
    for (int i = tid; i < TOT; i += stride) {
        float v = g_agg[i];
        s += v; ss += v * v;
    }
    __shared__ float sh[256], sh2[256];
    sh[threadIdx.x] = s; sh2[threadIdx.x] = ss;
    __syncthreads();
    if (threadIdx.x < 32) {
        for (int w = 1; w < 8; w++) { s += sh[w * 32 + lane]; ss += sh2[w * 32 + lane]; }
        atomicAdd(&g_sum[lane],   (double)s);
        atomicAdd(&g_sumsq[lane], (double)ss);
    }
}

// ---------------- finalize BN params ----------------
__global__ void k_final(const float* __restrict__ gamma, const float* __restrict__ beta) {
    int c = threadIdx.x;
    if (c < CC) {
        double cnt  = (double)NB * NN * TT;
        double mean = g_sum[c] / cnt;
        double var  = g_sumsq[c] / cnt - mean * mean;
        float sc = gamma[c] * rsqrtf((float)var + 1e-5f);
        g_scale[c] = sc;
        g_shift[c] = beta[c] - (float)mean * sc;
    }
}

// ---------------- transpose + normalize + relu -> out[B][C][N][T] ----------------
#define CHUNK 16
__global__ void k_out(float* __restrict__ out) {
    __shared__ __align__(16) float tile[CHUNK * TT * 33];  // [j=0..191][c padded 33]
    __shared__ float sc[CC], sf[CC];
    int b     = blockIdx.x / (NN / CHUNK);
    int chunk = blockIdx.x % (NN / CHUNK);
    int n0 = chunk * CHUNK;
    int tid = threadIdx.x;
    if (tid < CC) { sc[tid] = g_scale[tid]; sf[tid] = g_shift[tid]; }

    const float* src = &g_agg[((size_t)b * NN + n0) * FF];
    for (int i = tid; i < CHUNK * FF; i += 256) {
        tile[(i >> 5) * 33 + (i & 31)] = src[i];
    }
    __syncthreads();

    float* ob = out + (size_t)b * CC * NN * TT + n0 * TT;
    const int JD = CHUNK * TT;  // 192
    for (int i = tid; i < CHUNK * FF; i += 256) {
        int c = i / JD;
        int j = i % JD;
        float v = fmaf(tile[j * 33 + c], sc[c], sf[c]);
        ob[(size_t)c * NN * TT + j] = fmaxf(v, 0.f);
    }
}

extern "C" void kernel_launch(void* const* d_in, const int* in_sizes, int n_in,
                              void* d_out, int out_size) {
    const float* x     = (const float*)d_in[0];
    const void*  ei    = (const void*)d_in[1];
    const float* ew    = (const float*)d_in[2];
    const float* W     = (const float*)d_in[3];
    const float* bias  = (const float*)d_in[4];
    const float* gamma = (const float*)d_in[5];
    const float* beta  = (const float*)d_in[6];
    float* out = (float*)d_out;

    int E = in_sizes[2];   // edge_weight element count == E

    k_detect<<<1, 1024>>>((const int*)ei, E);
    k_zero<<<(NN + 256) / 256, 256>>>();
    k_linear<<<(BNT + 255) / 256, 256>>>(x, W);
    k_hist<<<(E + 255) / 256, 256>>>(ei, E);
    k_scan<<<1, 1024>>>();
    k_fill<<<(E + 255) / 256, 256>>>(ei, ew, E);
    k_gather<<<(NB * NN * 32 + 255) / 256, 256>>>(bias);
    k_stats<<<512, 256>>>();
    k_final<<<1, 32>>>(gamma, beta);
    k_out<<<NB * (NN / CHUNK), 256>>>(out);
}

// round 9
// speedup vs baseline: 1.0370x; 1.0370x over previous
#include <cuda_runtime.h>
#include <cuda_fp16.h>

// Problem constants (fixed shapes for this problem)
#define NB 4       // batch
#define CC 32      // channels (C_in == C_out)
#define NN 10000   // nodes
#define TT 12      // time steps
#define EMAX 160000
#define FF (CC*TT)         // 384 features per (b,n)
#define BNT (NB*NN*TT)     // 480000
#define TOT (NB*NN*FF)     // 15,360,000
#define ROWU4 (FF/8)       // 48 uint4 per feature row (fp16)

// Scratch (device globals; no allocation allowed)
__device__ __align__(16) __half g_h  [TOT];   // [B][N][T][C] fp16
__device__ __align__(16) float  g_agg[TOT];   // [B][N][T][C] fp32
__device__ int    g_deg[NN+1];
__device__ int    g_row[NN+1];
__device__ int    g_cur[NN];
__device__ int    g_srcs[EMAX];
__device__ float  g_ws  [EMAX];
__device__ double g_sum [CC];
__device__ double g_sumsq[CC];
__device__ float  g_scale[CC];
__device__ float  g_shift[CC];
__device__ int    g_is64;

// ---------------- detect edge_index dtype (int32 vs int64) ----------------
__global__ void k_detect(const int* __restrict__ ei, int E) {
    __shared__ int cnt;
    if (threadIdx.x == 0) cnt = 0;
    __syncthreads();
    int local = 0;
    for (int i = threadIdx.x; i < E; i += blockDim.x)
        if (ei[2 * i + 1] != 0) local++;
    for (int off = 16; off; off >>= 1)
        local += __shfl_down_sync(0xffffffffu, local, off);
    if ((threadIdx.x & 31) == 0 && local) atomicAdd(&cnt, local);
    __syncthreads();
    if (threadIdx.x == 0) g_is64 = (cnt == 0) ? 1 : 0;
}

__device__ __forceinline__ int load_idx(const void* eiv, long long pos) {
    if (g_is64) return (int)((const long long*)eiv)[pos];
    return ((const int*)eiv)[pos];
}

// ---------------- zero counters ----------------
__global__ void k_zero() {
    int i = blockIdx.x * blockDim.x + threadIdx.x;
    if (i < NN + 1) g_deg[i] = 0;
    if (i < CC) { g_sum[i] = 0.0; g_sumsq[i] = 0.0; }
}

// ---------------- linear: h[b][n][t][c] = sum_ci x[b][ci][n][t] * W[ci][c] (fp16 out) ----------------
__global__ void k_linear(const float* __restrict__ x, const float* __restrict__ W) {
    __shared__ __align__(16) float ws[CC * CC];
    int tid = threadIdx.x;
    for (int i = tid; i < CC * CC; i += blockDim.x) ws[i] = W[i];
    __syncthreads();

    int gid = blockIdx.x * blockDim.x + tid;   // enumerates (b, n, t)
    if (gid >= BNT) return;
    int b = gid / (NN * TT);
    int r = gid % (NN * TT);                   // n*TT + t

    const float* xp = x + (size_t)b * CC * NN * TT + r;
    float xv[CC];
#pragma unroll
    for (int c = 0; c < CC; c++) xv[c] = xp[c * (NN * TT)];

    float4 acc[8];
#pragma unroll
    for (int d = 0; d < 8; d++) acc[d] = make_float4(0.f, 0.f, 0.f, 0.f);

    const float4* w4 = (const float4*)ws;      // [c][8] float4 rows of W
#pragma unroll
    for (int c = 0; c < CC; c++) {
        float xc = xv[c];
#pragma unroll
        for (int d = 0; d < 8; d++) {
            float4 w = w4[c * 8 + d];
            acc[d].x = fmaf(xc, w.x, acc[d].x);
            acc[d].y = fmaf(xc, w.y, acc[d].y);
            acc[d].z = fmaf(xc, w.z, acc[d].z);
            acc[d].w = fmaf(xc, w.w, acc[d].w);
        }
    }

    // pack 32 floats -> 32 halfs -> 4 uint4 stores
    uint4* hp = (uint4*)g_h + (size_t)gid * 4;
#pragma unroll
    for (int j = 0; j < 4; j++) {
        __half2 p0 = __floats2half2_rn(acc[2 * j].x,     acc[2 * j].y);
        __half2 p1 = __floats2half2_rn(acc[2 * j].z,     acc[2 * j].w);
        __half2 p2 = __floats2half2_rn(acc[2 * j + 1].x, acc[2 * j + 1].y);
        __half2 p3 = __floats2half2_rn(acc[2 * j + 1].z, acc[2 * j + 1].w);
        uint4 o;
        o.x = *reinterpret_cast<unsigned*>(&p0);
        o.y = *reinterpret_cast<unsigned*>(&p1);
        o.z = *reinterpret_cast<unsigned*>(&p2);
        o.w = *reinterpret_cast<unsigned*>(&p3);
        hp[j] = o;
    }
}

// ---------------- degree histogram ----------------
__global__ void k_hist(const void* __restrict__ eiv, int E) {
    int e = blockIdx.x * blockDim.x + threadIdx.x;
    if (e >= E) return;
    int dst = load_idx(eiv, (long long)E + e);
    if ((unsigned)dst < NN) atomicAdd(&g_deg[dst], 1);
}

// ---------------- exclusive scan over degrees (single block) ----------------
__global__ void k_scan() {
    __shared__ int sp[1024];
    int tid = threadIdx.x;
    const int CH = (NN + 1023) / 1024;  // 10
    int base = tid * CH;
    int s = 0;
    for (int k = 0; k < CH; k++) { int i = base + k; if (i < NN) s += g_deg[i]; }
    sp[tid] = s;
    __syncthreads();
    for (int off = 1; off < 1024; off <<= 1) {
        int v = (tid >= off) ? sp[tid - off] : 0;
        __syncthreads();
        sp[tid] += v;
        __syncthreads();
    }
    int run = sp[tid] - s;  // exclusive prefix of this chunk
    for (int k = 0; k < CH; k++) {
        int i = base + k;
        if (i < NN) { g_row[i] = run; g_cur[i] = run; run += g_deg[i]; }
    }
    if (tid == 1023) g_row[NN] = sp[1023];
}

// ---------------- fill CSR ----------------
__global__ void k_fill(const void* __restrict__ eiv, const float* __restrict__ ew, int E) {
    int e = blockIdx.x * blockDim.x + threadIdx.x;
    if (e >= E) return;
    int dst = load_idx(eiv, (long long)E + e);
    if ((unsigned)dst >= NN) return;          // matches k_hist skip
    int src = load_idx(eiv, e);
    int p = atomicAdd(&g_cur[dst], 1);
    if ((unsigned)src < NN) {
        g_srcs[p] = src;
        g_ws[p]   = ew[e];
    } else {                                  // keep CSR slot consistent, zero-weight
        g_srcs[p] = 0;
        g_ws[p]   = 0.f;
    }
}

// ---------------- gather (fp16 source, fp32 accum) ----------------
// Note: bias is intentionally dropped — a per-channel constant shift is exactly
// cancelled by the training-mode BatchNorm that follows (y - mean(y)).
__device__ __forceinline__ void fma8(float2* a, uint4 v, float w) {
    unsigned u[4] = { v.x, v.y, v.z, v.w };
#pragma unroll
    for (int k = 0; k < 4; k++) {
        float2 f = __half22float2(*reinterpret_cast<__half2*>(&u[k]));
        a[k].x = fmaf(w, f.x, a[k].x);
        a[k].y = fmaf(w, f.y, a[k].y);
    }
}

__global__ void k_gather() {
    int wid  = (blockIdx.x * blockDim.x + threadIdx.x) >> 5;
    int lane = threadIdx.x & 31;
    if (wid >= NB * NN) return;
    int b = wid / NN;
    int n = wid % NN;
    bool second = (lane < 16);

    float2 a0[4], a1[4];
#pragma unroll
    for (int k = 0; k < 4; k++) { a0[k] = make_float2(0.f, 0.f); a1[k] = make_float2(0.f, 0.f); }

    int e0 = g_row[n], e1 = g_row[n + 1];
    const uint4* hb = (const uint4*)g_h;
    int rb = b * NN;

    for (int e = e0; e < e1; e++) {
        float w = g_ws[e];
        const uint4* hr = hb + (size_t)(rb + g_srcs[e]) * ROWU4;
        uint4 v0 = hr[lane];
        fma8(a0, v0, w);
        if (second) {
            uint4 v1 = hr[32 + lane];
            fma8(a1, v1, w);
        }
    }

    // chunk `lane` covers floats [lane*8, lane*8+8) of the fp32 agg row
    float4* ap = (float4*)&g_agg[(size_t)(rb + n) * FF];
    ap[lane * 2]     = make_float4(a0[0].x, a0[0].y, a0[1].x, a0[1].y);
    ap[lane * 2 + 1] = make_float4(a0[2].x, a0[2].y, a0[3].x, a0[3].y);
    if (second) {
        ap[(32 + lane) * 2]     = make_float4(a1[0].x, a1[0].y, a1[1].x, a1[1].y);
        ap[(32 + lane) * 2 + 1] = make_float4(a1[2].x, a1[2].y, a1[3].x, a1[3].y);
    }
}

// ---------------- per-channel sum / sumsq ----------------
__global__ void k_stats() {
    int tid = blockIdx.x * blockDim.x + threadIdx.x;
    int stride = gridDim.x * blockDim.x;   // multiple of 32
    int lane = threadIdx.x & 31;
    float s = 0.f, ss = 0.f;
    for (int i = tid; i < TOT; i += stride) {
        float v = g_agg[i];
        s += v; ss += v * v;
    }
    __shared__ float sh[256], sh2[256];
    sh[threadIdx.x] = s; sh2[threadIdx.x] = ss;
    __syncthreads();
    if (threadIdx.x < 32) {
        for (int w = 1; w < 8; w++) { s += sh[w * 32 + lane]; ss += sh2[w * 32 + lane]; }
        atomicAdd(&g_sum[lane],   (double)s);
        atomicAdd(&g_sumsq[lane], (double)ss);
    }
}

// ---------------- finalize BN params ----------------
__global__ void k_final(const float* __restrict__ gamma, const float* __restrict__ beta) {
    int c = threadIdx.x;
    if (c < CC) {
        double cnt  = (double)NB * NN * TT;
        double mean = g_sum[c] / cnt;
        double var  = g_sumsq[c] / cnt - mean * mean;
        float sc = gamma[c] * rsqrtf((float)var + 1e-5f);
        g_scale[c] = sc;
        g_shift[c] = beta[c] - (float)mean * sc;
    }
}

// ---------------- transpose + normalize + relu -> out[B][C][N][T] ----------------
#define CHUNK 16
__global__ void k_out(float* __restrict__ out) {
    __shared__ __align__(16) float tile[CHUNK * TT * 33];  // [j=0..191][c padded 33]
    __shared__ float sc[CC], sf[CC];
    int b     = blockIdx.x / (NN / CHUNK);
    int chunk = blockIdx.x % (NN / CHUNK);
    int n0 = chunk * CHUNK;
    int tid = threadIdx.x;
    if (tid < CC) { sc[tid] = g_scale[tid]; sf[tid] = g_shift[tid]; }

    const float* src = &g_agg[((size_t)b * NN + n0) * FF];
    for (int i = tid; i < CHUNK * FF; i += 256) {
        tile[(i >> 5) * 33 + (i & 31)] = src[i];
    }
    __syncthreads();

    float* ob = out + (size_t)b * CC * NN * TT + n0 * TT;
    const int JD = CHUNK * TT;  // 192
    for (int i = tid; i < CHUNK * FF; i += 256) {
        int c = i / JD;
        int j = i % JD;
        float v = fmaf(tile[j * 33 + c], sc[c], sf[c]);
        ob[(size_t)c * NN * TT + j] = fmaxf(v, 0.f);
    }
}

extern "C" void kernel_launch(void* const* d_in, const int* in_sizes, int n_in,
                              void* d_out, int out_size) {
    const float* x     = (const float*)d_in[0];
    const void*  ei    = (const void*)d_in[1];
    const float* ew    = (const float*)d_in[2];
    const float* W     = (const float*)d_in[3];
    const float* gamma = (const float*)d_in[5];
    const float* beta  = (const float*)d_in[6];
    float* out = (float*)d_out;

    int E = in_sizes[2];   // edge_weight element count == E

    k_detect<<<1, 1024>>>((const int*)ei, E);
    k_zero<<<(NN + 256) / 256, 256>>>();
    k_linear<<<(BNT + 255) / 256, 256>>>(x, W);
    k_hist<<<(E + 255) / 256, 256>>>(ei, E);
    k_scan<<<1, 1024>>>();
    k_fill<<<(E + 255) / 256, 256>>>(ei, ew, E);
    k_gather<<<(NB * NN * 32 + 255) / 256, 256>>>();
    k_stats<<<512, 256>>>();
    k_final<<<1, 32>>>(gamma, beta);
    k_out<<<NB * (NN / CHUNK), 256>>>(out);
}

// round 13
// speedup vs baseline: 1.4521x; 1.4003x over previous
#include <cuda_runtime.h>
#include <cuda_fp16.h>

// Problem constants (fixed shapes for this problem)
#define NB 4       // batch
#define CC 32      // channels (C_in == C_out)
#define NN 10000   // nodes
#define TT 12      // time steps
#define EMAX 160000
#define FF (CC*TT)          // 384 features per (b,n)
#define BNT (NB*NN*TT)      // 480000
#define TOT (NB*NN*FF)      // 15,360,000
#define NROW (NB*FF)        // 1536 halfs per node (all batches)
#define NROWU4 (NROW/8)     // 192 uint4 per node row (fp16)

// Scratch (device globals; no allocation allowed)
// Layout: node-major so one warp serves all batches of a node.
__device__ __align__(16) __half g_h  [TOT];   // [N][B][T][C] fp16
__device__ __align__(16) float  g_agg[TOT];   // [N][B][T][C] fp32
__device__ int    g_deg[NN+1];
__device__ int    g_row[NN+1];
__device__ int    g_cur[NN];
__device__ int    g_srcs[EMAX];
__device__ float  g_ws  [EMAX];
__device__ double g_sum [CC];
__device__ double g_sumsq[CC];
__device__ float  g_scale[CC];
__device__ float  g_shift[CC];
__device__ int    g_nz;     // 0 => edge_index is int64 (all high words zero)

// ---------------- zero counters (runs BEFORE detect: also zeroes g_nz) ----------------
__global__ void k_zero() {
    int i = blockIdx.x * blockDim.x + threadIdx.x;
    if (i < NN + 1) g_deg[i] = 0;
    if (i < CC) { g_sum[i] = 0.0; g_sumsq[i] = 0.0; }
    if (i == 0) g_nz = 0;
}

// ---------------- detect edge_index dtype (int32 vs int64), multi-block ----------------
// Under int64 layout the high word of every 64-bit slot is 0 (indices < 2^31).
// Under int32 layout those words are arbitrary node indices — essentially never
// all zero across E samples. Reads only the first 2E int32 words (in-bounds
// under both interpretations).
__global__ void k_detect(const int* __restrict__ ei, int E) {
    int i = blockIdx.x * blockDim.x + threadIdx.x;
    int stride = gridDim.x * blockDim.x;
    int nz = 0;
    for (; i < E; i += stride) nz |= ei[2 * i + 1];
    if (__any_sync(0xffffffffu, nz != 0) && (threadIdx.x & 31) == 0)
        g_nz = 1;   // race-free: only ever set to 1
}

__device__ __forceinline__ int load_idx(const void* eiv, long long pos) {
    if (g_nz == 0) return (int)((const long long*)eiv)[pos];
    return ((const int*)eiv)[pos];
}

// ---------------- linear: h[n][b][t][c] = sum_ci x[b][ci][n][t] * W[ci][c] (fp16 out) ----------------
__global__ void k_linear(const float* __restrict__ x, const float* __restrict__ W) {
    __shared__ __align__(16) float ws[CC * CC];
    int tid = threadIdx.x;
    for (int i = tid; i < CC * CC; i += blockDim.x) ws[i] = W[i];
    __syncthreads();

    int gid = blockIdx.x * blockDim.x + tid;   // enumerates (b, n, t) — b major for coalesced x reads
    if (gid >= BNT) return;
    int b = gid / (NN * TT);
    int r = gid % (NN * TT);                   // n*TT + t
    int n = r / TT;
    int t = r % TT;

    const float* xp = x + (size_t)b * CC * NN * TT + r;
    float xv[CC];
#pragma unroll
    for (int c = 0; c < CC; c++) xv[c] = xp[c * (NN * TT)];

    float4 acc[8];
#pragma unroll
    for (int d = 0; d < 8; d++) acc[d] = make_float4(0.f, 0.f, 0.f, 0.f);

    const float4* w4 = (const float4*)ws;      // [c][8] float4 rows of W
#pragma unroll
    for (int c = 0; c < CC; c++) {
        float xc = xv[c];
#pragma unroll
        for (int d = 0; d < 8; d++) {
            float4 w = w4[c * 8 + d];
            acc[d].x = fmaf(xc, w.x, acc[d].x);
            acc[d].y = fmaf(xc, w.y, acc[d].y);
            acc[d].z = fmaf(xc, w.z, acc[d].z);
            acc[d].w = fmaf(xc, w.w, acc[d].w);
        }
    }

    // pack 32 floats -> 32 halfs -> 4 uint4 stores at node-major offset
    uint4* hp = (uint4*)g_h + ((size_t)n * NB + b) * (FF / 8) + t * 4;
#pragma unroll
    for (int j = 0; j < 4; j++) {
        __half2 p0 = __floats2half2_rn(acc[2 * j].x,     acc[2 * j].y);
        __half2 p1 = __floats2half2_rn(acc[2 * j].z,     acc[2 * j].w);
        __half2 p2 = __floats2half2_rn(acc[2 * j + 1].x, acc[2 * j + 1].y);
        __half2 p3 = __floats2half2_rn(acc[2 * j + 1].z, acc[2 * j + 1].w);
        uint4 o;
        o.x = *reinterpret_cast<unsigned*>(&p0);
        o.y = *reinterpret_cast<unsigned*>(&p1);
        o.z = *reinterpret_cast<unsigned*>(&p2);
        o.w = *reinterpret_cast<unsigned*>(&p3);
        hp[j] = o;
    }
}

// ---------------- degree histogram ----------------
__global__ void k_hist(const void* __restrict__ eiv, int E) {
    int e = blockIdx.x * blockDim.x + threadIdx.x;
    if (e >= E) return;
    int dst = load_idx(eiv, (long long)E + e);
    if ((unsigned)dst < NN) atomicAdd(&g_deg[dst], 1);
}

// ---------------- exclusive scan over degrees (single block) ----------------
__global__ void k_scan() {
    __shared__ int sp[1024];
    int tid = threadIdx.x;
    const int CH = (NN + 1023) / 1024;  // 10
    int base = tid * CH;
    int s = 0;
    for (int k = 0; k < CH; k++) { int i = base + k; if (i < NN) s += g_deg[i]; }
    sp[tid] = s;
    __syncthreads();
    for (int off = 1; off < 1024; off <<= 1) {
        int v = (tid >= off) ? sp[tid - off] : 0;
        __syncthreads();
        sp[tid] += v;
        __syncthreads();
    }
    int run = sp[tid] - s;  // exclusive prefix of this chunk
    for (int k = 0; k < CH; k++) {
        int i = base + k;
        if (i < NN) { g_row[i] = run; g_cur[i] = run; run += g_deg[i]; }
    }
    if (tid == 1023) g_row[NN] = sp[1023];
}

// ---------------- fill CSR ----------------
__global__ void k_fill(const void* __restrict__ eiv, const float* __restrict__ ew, int E) {
    int e = blockIdx.x * blockDim.x + threadIdx.x;
    if (e >= E) return;
    int dst = load_idx(eiv, (long long)E + e);
    if ((unsigned)dst >= NN) return;          // matches k_hist skip
    int src = load_idx(eiv, e);
    int p = atomicAdd(&g_cur[dst], 1);
    if ((unsigned)src < NN) {
        g_srcs[p] = src;
        g_ws[p]   = ew[e];
    } else {                                  // keep CSR slot consistent, zero-weight
        g_srcs[p] = 0;
        g_ws[p]   = 0.f;
    }
}

// ---------------- gather (fp16 source, fp32 accum), one warp per node, all batches ----------------
// Bias is intentionally dropped: a per-channel constant shift is exactly
// cancelled by the training-mode BatchNorm that follows (y - mean(y)).
__device__ __forceinline__ void fma8(float2* a, uint4 v, float w) {
    unsigned u[4] = { v.x, v.y, v.z, v.w };
#pragma unroll
    for (int k = 0; k < 4; k++) {
        float2 f = __half22float2(*reinterpret_cast<__half2*>(&u[k]));
        a[k].x = fmaf(w, f.x, a[k].x);
        a[k].y = fmaf(w, f.y, a[k].y);
    }
}

__global__ __launch_bounds__(128) void k_gather() {
    int n    = (blockIdx.x * blockDim.x + threadIdx.x) >> 5;
    int lane = threadIdx.x & 31;
    if (n >= NN) return;

    float2 acc[24];                           // 48 floats = this lane's slice of 4 batch rows
#pragma unroll
    for (int k = 0; k < 24; k++) acc[k] = make_float2(0.f, 0.f);

    int e0 = g_row[n], e1 = g_row[n + 1];
    const uint4* hb = (const uint4*)g_h;

    for (int e = e0; e < e1; e++) {
        float w = g_ws[e];
        const uint4* hr = hb + (size_t)g_srcs[e] * NROWU4;
        uint4 v[6];
#pragma unroll
        for (int j = 0; j < 6; j++) v[j] = hr[lane + 32 * j];   // 6 independent 16B loads
#pragma unroll
        for (int j = 0; j < 6; j++) fma8(&acc[j * 4], v[j], w);
    }

    // uint4 j covers floats [8*(lane+32j), +8) of the node's 1536-float agg row
    float4* ap = (float4*)&g_agg[(size_t)n * NROW];
#pragma unroll
    for (int j = 0; j < 6; j++) {
        int p = lane + 32 * j;
        ap[2 * p]     = make_float4(acc[4*j].x,   acc[4*j].y,   acc[4*j+1].x, acc[4*j+1].y);
        ap[2 * p + 1] = make_float4(acc[4*j+2].x, acc[4*j+2].y, acc[4*j+3].x, acc[4*j+3].y);
    }
}

// ---------------- per-channel sum / sumsq (layout-invariant: C innermost, 32-aligned) ----------------
__global__ void k_stats() {
    int tid = blockIdx.x * blockDim.x + threadIdx.x;
    int stride = gridDim.x * blockDim.x;   // multiple of 32
    int lane = threadIdx.x & 31;
    float s = 0.f, ss = 0.f;
    for (int i = tid; i < TOT; i += stride) {
        float v = g_agg[i];
        s += v; ss += v * v;
    }
    __shared__ float sh[256], sh2[256];
    sh[threadIdx.x] = s; sh2[threadIdx.x] = ss;
    __syncthreads();
    if (threadIdx.x < 32) {
        for (int w = 1; w < 8; w++) { s += sh[w * 32 + lane]; ss += sh2[w * 32 + lane]; }
        atomicAdd(&g_sum[lane],   (double)s);
        atomicAdd(&g_sumsq[lane], (double)ss);
    }
}

// ---------------- finalize BN params ----------------
__global__ void k_final(const float* __restrict__ gamma, const float* __restrict__ beta) {
    int c = threadIdx.x;
    if (c < CC) {
        double cnt  = (double)NB * NN * TT;
        double mean = g_sum[c] / cnt;
        double var  = g_sumsq[c] / cnt - mean * mean;
        float sc = gamma[c] * rsqrtf((float)var + 1e-5f);
        g_scale[c] = sc;
        g_shift[c] = beta[c] - (float)mean * sc;
    }
}

// ---------------- transpose + normalize + relu -> out[B][C][N][T] ----------------
#define CHUNK 16
__global__ void k_out(float* __restrict__ out) {
    __shared__ __align__(16) float tile[CHUNK * TT * 33];  // [j=0..191][c padded 33]
    __shared__ float sc[CC], sf[CC];
    int b     = blockIdx.x / (NN / CHUNK);
    int chunk = blockIdx.x % (NN / CHUNK);
    int n0 = chunk * CHUNK;
    int tid = threadIdx.x;
    if (tid < CC) { sc[tid] = g_scale[tid]; sf[tid] = g_shift[tid]; }

    // source rows are node-major: row for (node n0+i, batch b) at ((n0+i)*NB + b)*FF
    for (int i = tid; i < CHUNK * FF; i += 256) {
        int nd = i / FF;
        int f  = i % FF;
        float v = g_agg[((size_t)(n0 + nd) * NB + b) * FF + f];
        tile[(i >> 5) * 33 + (i & 31)] = v;
    }
    __syncthreads();

    float* ob = out + (size_t)b * CC * NN * TT + n0 * TT;
    const int JD = CHUNK * TT;  // 192
    for (int i = tid; i < CHUNK * FF; i += 256) {
        int c = i / JD;
        int j = i % JD;
        float v = fmaf(tile[j * 33 + c], sc[c], sf[c]);
        ob[(size_t)c * NN * TT + j] = fmaxf(v, 0.f);
    }
}

extern "C" void kernel_launch(void* const* d_in, const int* in_sizes, int n_in,
                              void* d_out, int out_size) {
    const float* x     = (const float*)d_in[0];
    const void*  ei    = (const void*)d_in[1];
    const float* ew    = (const float*)d_in[2];
    const float* W     = (const float*)d_in[3];
    const float* gamma = (const float*)d_in[5];
    const float* beta  = (const float*)d_in[6];
    float* out = (float*)d_out;

    int E = in_sizes[2];   // edge_weight element count == E

    k_zero<<<(NN + 256) / 256, 256>>>();
    k_detect<<<160, 256>>>((const int*)ei, E);
    k_linear<<<(BNT + 255) / 256, 256>>>(x, W);
    k_hist<<<(E + 255) / 256, 256>>>(ei, E);
    k_scan<<<1, 1024>>>();
    k_fill<<<(E + 255) / 256, 256>>>(ei, ew, E);
    k_gather<<<(NN * 32 + 127) / 128, 128>>>();
    k_stats<<<512, 256>>>();
    k_final<<<1, 32>>>(gamma, beta);
    k_out<<<NB * (NN / CHUNK), 256>>>(out);
}